// round 15
// baseline (speedup 1.0000x reference)
#include <cuda_runtime.h>

#define NN   500000
#define EE   8000000
#define DD   10
#define GG   5000
#define CAP  2048                // slots per gid; overflow lossless via fallback
#define SL   8                   // warp-slices per gid in gather
#define BN_EPS 1e-5f
#define GPB  34                  // output graphs per head block (148*34=5032 >= 5000)

// ---- scratch (no allocations allowed) ----
__device__ int    d_is64;
__device__ int    d_cnt[GG];               // scatter cursors
__device__ int    d_ncnt[GG];              // node count per graph (binary-searched)
__device__ float2 d_sorted[GG * CAP];      // {w, src-as-float} grouped by gid (80MB)
__device__ float  d_gacc[GG * DD];

// ---- init: per-block dtype detect, zero cursors/acc, node counts via binary search ----
__global__ void k_init(const int* __restrict__ ei, const int* __restrict__ bv) {
    __shared__ int s_is64;
    if (threadIdx.x == 0) {
        int is64 = 1;
        #pragma unroll
        for (int k = 1; k < 64; k += 2)
            if (ei[k] != 0) { is64 = 0; break; }
        s_is64 = is64;
        if (blockIdx.x == 0) d_is64 = is64;
    }
    __syncthreads();
    const int sh = s_is64;
    int i = blockIdx.x * blockDim.x + threadIdx.x;
    if (i < GG * DD) d_gacc[i] = 0.f;
    if (i < GG) {
        d_cnt[i] = 0;
        int lo = 0, hi = NN;
        while (lo < hi) { int mid = (lo + hi) >> 1; if (bv[(size_t)mid << sh] <  i) lo = mid + 1; else hi = mid; }
        int lb = lo;
        lo = 0; hi = NN;
        while (lo < hi) { int mid = (lo + hi) >> 1; if (bv[(size_t)mid << sh] <= i) lo = mid + 1; else hi = mid; }
        int c = lo - lb; if (c < 1) c = 1;
        d_ncnt[i] = c;
    }
}

// ---- phase A: counting-scatter into per-gid buckets; overflow -> direct atomics ----
__global__ void __launch_bounds__(512) k_scat(const float* __restrict__ x,
                                              const int* __restrict__ ei32,
                                              const float* __restrict__ attr,
                                              const int* __restrict__ b32) {
    int e = blockIdx.x * blockDim.x + threadIdx.x;
    if (e >= EE) return;
    const int s = d_is64;
    int   src = ei32[(size_t)e << s];
    int   dst = ei32[((size_t)EE + (size_t)e) << s];
    float w   = attr[e];
    int   gid = __ldg(&b32[(size_t)dst << s]);
    int   pos = atomicAdd(&d_cnt[gid], 1);
    if (pos < CAP) {
        d_sorted[(size_t)gid * CAP + pos] = make_float2(w, __int_as_float(src));
    } else {
        const float* xr = x + (size_t)src * DD;
        float* gr = d_gacc + (size_t)gid * DD;
        #pragma unroll
        for (int d = 0; d < DD; d++) atomicAdd(gr + d, xr[d] * w);
    }
}

// ---- phase B: atomic-free accumulation; warp-slice per gid, feature-across-lanes ----
__global__ void __launch_bounds__(1024, 1) k_gath(const float* __restrict__ x) {
    int wg   = (blockIdx.x * 1024 + threadIdx.x) >> 5;
    int lane = threadIdx.x & 31;
    int gid   = wg >> 3;                                 // SL = 8
    int slice = wg & 7;
    if (gid >= GG) return;

    int cnt = d_cnt[gid]; if (cnt > CAP) cnt = CAP;      // overflow already in d_gacc
    int per = (cnt + SL - 1) / SL;
    int i0 = slice * per;
    int i1 = i0 + per; if (i1 > cnt) i1 = cnt;

    int j = lane / 10;                                   // 0..2 active; lanes 30,31 idle
    int d = lane - j * 10;

    const float2* row = d_sorted + (size_t)gid * CAP;
    float acc = 0.f;
    if (j < 3) {
        #pragma unroll 4
        for (int i = i0 + j; i < i1; i += 3) {
            float2 rec = __ldcs(&row[i]);                // stream buckets; keep x in L2
            int src = __float_as_int(rec.y);
            acc = fmaf(rec.x, x[src * DD + d], acc);
        }
    }
    float v1 = __shfl_sync(0xffffffffu, acc, d + 10);
    float v2 = __shfl_sync(0xffffffffu, acc, d + 20);
    if (lane < 10)
        atomicAdd(&d_gacc[gid * DD + lane], acc + v1 + v2);
}

// ---- fused MLP head: every block redundantly computes all graphs' activations
//      in smem -> block-local BN stats (no grid sync); writes its own GPB graphs ----
__global__ void __launch_bounds__(256, 1) k_head(
    const float* __restrict__ fc1_w,  const float* __restrict__ fc1_b,
    const float* __restrict__ fc2_w,  const float* __restrict__ fc2_b,
    const float* __restrict__ rfc1_w, const float* __restrict__ rfc1_b,
    const float* __restrict__ rfc2_w, const float* __restrict__ rfc2_b,
    const float* __restrict__ fco_w,  const float* __restrict__ fco_b,
    const float* __restrict__ bn1_g,  const float* __restrict__ bn1_b,
    const float* __restrict__ bn2_g,  const float* __restrict__ bn2_b,
    const float* __restrict__ rbn1_g, const float* __restrict__ rbn1_b,
    const float* __restrict__ rbn2_g, const float* __restrict__ rbn2_b,
    float* __restrict__ out)
{
    extern __shared__ float st[];                        // [GG*DD] pre-BN activations
    __shared__ float sW[DD * DD], sb[DD], sgm[DD], sbt[DD];
    __shared__ float sred[8][2 * DD];
    __shared__ float sstat[2 * DD];
    __shared__ float sres[GPB * DD];

    const int tid = threadIdx.x;
    const int wid = tid >> 5, lid = tid & 31;
    const int g0 = blockIdx.x * GPB;
    const int g1 = (g0 + GPB < GG) ? g0 + GPB : GG;

    const float* Ws[4]  = {fc1_w, fc2_w, rfc1_w, rfc2_w};
    const float* bs[4]  = {fc1_b, fc2_b, rfc1_b, rfc2_b};
    const float* gms[4] = {bn1_g, bn2_g, rbn1_g, rbn2_g};
    const float* bts[4] = {bn1_b, bn2_b, rbn1_b, rbn2_b};

    #pragma unroll 1
    for (int s = 0; s < 4; s++) {
        __syncthreads();
        if (tid < DD * DD) sW[tid] = Ws[s][tid];
        if (tid < DD) { sb[tid] = bs[s][tid]; }
        if (s >= 1 && tid < DD) { sgm[tid] = gms[s - 1][tid]; sbt[tid] = bts[s - 1][tid]; }
        __syncthreads();

        float ls[DD], lq[DD];
        #pragma unroll
        for (int o = 0; o < DD; o++) { ls[o] = 0.f; lq[o] = 0.f; }

        for (int g = tid; g < GG; g += 256) {
            float y[DD];
            if (s == 0) {
                float inv = 1.f / (float)d_ncnt[g];
                #pragma unroll
                for (int dd = 0; dd < DD; dd++) y[dd] = d_gacc[g * DD + dd] * inv;
            } else {
                #pragma unroll
                for (int o = 0; o < DD; o++) {
                    float t = st[g * DD + o];
                    float m = sstat[o] * (1.f / GG);
                    float q = sstat[DD + o] * (1.f / GG);
                    float v = q - m * m;
                    y[o] = fmaxf(sgm[o] * (t - m) * rsqrtf(v + BN_EPS) + sbt[o], 0.f);
                }
                if (s == 2 && g >= g0 && g < g1) {       // stash residual y2 for own graphs
                    #pragma unroll
                    for (int o = 0; o < DD; o++) sres[(g - g0) * DD + o] = y[o];
                }
            }
            #pragma unroll
            for (int o = 0; o < DD; o++) {
                float a = sb[o];
                #pragma unroll
                for (int dd = 0; dd < DD; dd++) a = fmaf(sW[o * DD + dd], y[dd], a);
                st[g * DD + o] = a;
                ls[o] += a;
                lq[o] = fmaf(a, a, lq[o]);
            }
        }
        // block-local stats reduction
        #pragma unroll
        for (int o = 0; o < DD; o++) {
            #pragma unroll
            for (int off = 16; off > 0; off >>= 1) {
                ls[o] += __shfl_xor_sync(0xffffffffu, ls[o], off);
                lq[o] += __shfl_xor_sync(0xffffffffu, lq[o], off);
            }
        }
        if (lid < DD)          sred[wid][lid] = ls[lid];
        else if (lid < 2 * DD) sred[wid][lid] = lq[lid - DD];
        __syncthreads();
        if (tid < 2 * DD) {
            float a = 0.f;
            #pragma unroll
            for (int w = 0; w < 8; w++) a += sred[w][tid];
            sstat[tid] = a;
        }
    }

    // finale: y4 = relu(bn3(t_d) + res); out = fco(y4) + b  (own graphs only)
    __syncthreads();
    if (tid < DD) { sgm[tid] = rbn2_g[tid]; sbt[tid] = rbn2_b[tid]; sW[tid] = fco_w[tid]; }
    if (tid == 0) sb[0] = fco_b[0];
    __syncthreads();
    for (int g = g0 + tid; g < g1; g += 256) {
        float a = sb[0];
        #pragma unroll
        for (int o = 0; o < DD; o++) {
            float t = st[g * DD + o];
            float m = sstat[o] * (1.f / GG);
            float q = sstat[DD + o] * (1.f / GG);
            float v = q - m * m;
            float y = fmaxf(sgm[o] * (t - m) * rsqrtf(v + BN_EPS) + sbt[o]
                            + sres[(g - g0) * DD + o], 0.f);
            a = fmaf(y, sW[o], a);
        }
        out[g] = a;
    }
}

extern "C" void kernel_launch(void* const* d_in, const int* in_sizes, int n_in,
                              void* d_out, int out_size) {
    const float* x     = (const float*)d_in[0];
    const int*   ei32  = (const int*)d_in[1];
    const float* attr  = (const float*)d_in[2];
    const int*   b32   = (const int*)d_in[3];
    const float* fc1_w  = (const float*)d_in[4],  *fc1_b  = (const float*)d_in[5];
    const float* fc2_w  = (const float*)d_in[6],  *fc2_b  = (const float*)d_in[7];
    const float* rfc1_w = (const float*)d_in[8],  *rfc1_b = (const float*)d_in[9];
    const float* rfc2_w = (const float*)d_in[10], *rfc2_b = (const float*)d_in[11];
    const float* fco_w  = (const float*)d_in[12], *fco_b  = (const float*)d_in[13];
    const float* bn1_g  = (const float*)d_in[14], *bn1_b  = (const float*)d_in[15];
    const float* bn2_g  = (const float*)d_in[16], *bn2_b  = (const float*)d_in[17];
    const float* rbn1_g = (const float*)d_in[18], *rbn1_b = (const float*)d_in[19];
    const float* rbn2_g = (const float*)d_in[20], *rbn2_b = (const float*)d_in[21];
    float* out = (float*)d_out;

    static const int SMEM_HEAD = GG * DD * (int)sizeof(float);    // 200,000 B
    cudaFuncSetAttribute(k_head, cudaFuncAttributeMaxDynamicSharedMemorySize, SMEM_HEAD);

    k_init<<<(GG * DD + 255) / 256, 256>>>(ei32, b32);
    k_scat<<<(EE + 511) / 512, 512>>>(x, ei32, attr, b32);
    k_gath<<<(GG * SL * 32 + 1023) / 1024, 1024>>>(x);
    k_head<<<(GG + GPB - 1) / GPB, 256, SMEM_HEAD>>>(
        fc1_w, fc1_b, fc2_w, fc2_b, rfc1_w, rfc1_b, rfc2_w, rfc2_b,
        fco_w, fco_b, bn1_g, bn1_b, bn2_g, bn2_b,
        rbn1_g, rbn1_b, rbn2_g, rbn2_b, out);
}

// round 16
// speedup vs baseline: 1.1635x; 1.1635x over previous
#include <cuda_runtime.h>

#define NN   500000
#define EE   8000000
#define DD   10
#define GG   5000
#define SH   4                   // cursor shards per gid
#define CAPS 512                 // slots per shard (mean 400, +2.5 sigma; overflow lossless)
#define SL   8                   // warp-slices per gid in gather (2 per shard)
#define BN_EPS 1e-5f
#define NHB  20
#define NHT  256

// ---- scratch (no allocations allowed) ----
__device__ int    d_is64;
__device__ int    d_cnt[GG * SH];          // sharded scatter cursors
__device__ int    d_ncnt[GG];              // node count per graph
__device__ float2 d_sorted[GG * SH * CAPS]; // {w, src-as-float} bucketed (80MB)
__device__ float  d_gacc[GG * DD];
__device__ float  d_stats[4 * 2 * DD];
__device__ float  d_t[GG * DD];
__device__ float  d_res[GG * DD];

// ---- init: dtype detect, zero cursors/acc/stats, node counts via binary search ----
__global__ void k_init(const int* __restrict__ ei, const int* __restrict__ bv) {
    __shared__ int s_is64;
    if (threadIdx.x == 0) {
        int is64 = 1;
        #pragma unroll
        for (int k = 1; k < 64; k += 2)
            if (ei[k] != 0) { is64 = 0; break; }
        s_is64 = is64;
        if (blockIdx.x == 0) d_is64 = is64;
    }
    __syncthreads();
    const int sh = s_is64;
    int i = blockIdx.x * blockDim.x + threadIdx.x;
    if (i < GG * DD)    d_gacc[i]  = 0.f;
    if (i < GG * SH)    d_cnt[i]   = 0;
    if (i < 4 * 2 * DD) d_stats[i] = 0.f;
    if (i < GG) {
        int lo = 0, hi = NN;
        while (lo < hi) { int mid = (lo + hi) >> 1; if (bv[(size_t)mid << sh] <  i) lo = mid + 1; else hi = mid; }
        int lb = lo;
        lo = 0; hi = NN;
        while (lo < hi) { int mid = (lo + hi) >> 1; if (bv[(size_t)mid << sh] <= i) lo = mid + 1; else hi = mid; }
        int c = lo - lb; if (c < 1) c = 1;
        d_ncnt[i] = c;
    }
}

// ---- phase A: counting-scatter into sharded per-gid buckets ----
__global__ void __launch_bounds__(512) k_scat(const float* __restrict__ x,
                                              const int* __restrict__ ei32,
                                              const float* __restrict__ attr,
                                              const int* __restrict__ b32) {
    int e = blockIdx.x * blockDim.x + threadIdx.x;
    if (e >= EE) return;
    const int s = d_is64;
    int   src = ei32[(size_t)e << s];
    int   dst = ei32[((size_t)EE + (size_t)e) << s];
    float w   = attr[e];
    int   gid = __ldg(&b32[(size_t)dst << s]);
    int   shard = e & (SH - 1);
    int   pos = atomicAdd(&d_cnt[gid * SH + shard], 1);
    if (pos < CAPS) {
        d_sorted[(size_t)(gid * SH + shard) * CAPS + pos] = make_float2(w, __int_as_float(src));
    } else {
        const float* xr = x + (size_t)src * DD;
        float* gr = d_gacc + (size_t)gid * DD;
        #pragma unroll
        for (int d = 0; d < DD; d++) atomicAdd(gr + d, xr[d] * w);
    }
}

// ---- phase B: atomic-free accumulation; 2 warp-slices per shard, feature-across-lanes ----
__global__ void __launch_bounds__(1024, 1) k_gath(const float* __restrict__ x) {
    int wg    = (blockIdx.x * 1024 + threadIdx.x) >> 5;
    int lane  = threadIdx.x & 31;
    int gid   = wg >> 3;                                 // SL = 8
    int sub   = wg & 7;
    int shard = sub >> 1;
    int half  = sub & 1;
    if (gid >= GG) return;

    int cnt = d_cnt[gid * SH + shard]; if (cnt > CAPS) cnt = CAPS;
    int per = (cnt + 1) >> 1;
    int i0 = half * per;
    int i1 = i0 + per; if (i1 > cnt) i1 = cnt;

    int j = lane / 10;                                   // 0..2 active; lanes 30,31 idle
    int d = lane - j * 10;

    const float2* row = d_sorted + (size_t)(gid * SH + shard) * CAPS;
    float acc = 0.f;
    if (j < 3) {
        #pragma unroll 4
        for (int i = i0 + j; i < i1; i += 3) {
            float2 rec = __ldcs(&row[i]);
            int src = __float_as_int(rec.y);
            acc = fmaf(rec.x, x[src * DD + d], acc);
        }
    }
    float v1 = __shfl_sync(0xffffffffu, acc, d + 10);
    float v2 = __shfl_sync(0xffffffffu, acc, d + 20);
    if (lane < 10)
        atomicAdd(&d_gacc[gid * DD + lane], acc + v1 + v2);
}

// ---- MLP head stage kernel (5 launches; kernel boundaries = global sync) ----
__global__ void __launch_bounds__(NHT, 1) k_stage(
    int s,
    const float* __restrict__ W,   const float* __restrict__ bias,
    const float* __restrict__ gpr, const float* __restrict__ bpr,
    float* __restrict__ outp)
{
    __shared__ float sW[DD * DD], sb[DD], sgm[DD], sbt[DD], sst[2 * DD];
    __shared__ float sred[NHT / 32][2 * DD];
    const int tid = threadIdx.x;
    const int wid = tid >> 5, lid = tid & 31;
    const int g = blockIdx.x * NHT + tid;
    const bool act = (g < GG);

    if (s < 4) {
        if (tid < DD * DD) sW[tid] = W[tid];
        if (tid < DD) sb[tid] = bias[tid];
    } else {
        if (tid < DD) sW[tid] = W[tid];
        if (tid == 0) sb[0] = bias[0];
    }
    if (s >= 1) {
        if (tid < DD) { sgm[tid] = gpr[tid]; sbt[tid] = bpr[tid]; }
        if (tid < 2 * DD) sst[tid] = d_stats[(s - 1) * 2 * DD + tid];
    }
    __syncthreads();

    float y[DD];
    if (s == 0) {
        if (act) {
            float inv = 1.f / (float)d_ncnt[g];
            #pragma unroll
            for (int dd = 0; dd < DD; dd++) y[dd] = d_gacc[g * DD + dd] * inv;
        } else {
            #pragma unroll
            for (int dd = 0; dd < DD; dd++) y[dd] = 0.f;
        }
    } else {
        #pragma unroll
        for (int o = 0; o < DD; o++) {
            float t = act ? d_t[g * DD + o] : 0.f;
            float m = sst[o] * (1.f / GG);
            float q = sst[DD + o] * (1.f / GG);
            float v = q - m * m;
            float val = sgm[o] * (t - m) * rsqrtf(v + BN_EPS) + sbt[o];
            if (s == 4 && act) val += d_res[g * DD + o];
            y[o] = fmaxf(val, 0.f);
        }
        if (s == 2 && act) {
            #pragma unroll
            for (int o = 0; o < DD; o++) d_res[g * DD + o] = y[o];
        }
    }

    if (s == 4) {
        if (act) {
            float a = sb[0];
            #pragma unroll
            for (int dd = 0; dd < DD; dd++) a = fmaf(y[dd], sW[dd], a);
            outp[g] = a;
        }
        return;
    }

    float o_[DD];
    #pragma unroll
    for (int o = 0; o < DD; o++) {
        float a = sb[o];
        #pragma unroll
        for (int dd = 0; dd < DD; dd++) a = fmaf(sW[o * DD + dd], y[dd], a);
        o_[o] = act ? a : 0.f;
        if (act) d_t[g * DD + o] = a;
    }

    float ls[DD], lq[DD];
    #pragma unroll
    for (int o = 0; o < DD; o++) {
        ls[o] = o_[o]; lq[o] = o_[o] * o_[o];
        #pragma unroll
        for (int off = 16; off > 0; off >>= 1) {
            ls[o] += __shfl_xor_sync(0xffffffffu, ls[o], off);
            lq[o] += __shfl_xor_sync(0xffffffffu, lq[o], off);
        }
    }
    if (lid < DD)          sred[wid][lid] = ls[lid];
    else if (lid < 2 * DD) sred[wid][lid] = lq[lid - DD];
    __syncthreads();
    if (tid < 2 * DD) {
        float a = 0.f;
        #pragma unroll
        for (int w = 0; w < NHT / 32; w++) a += sred[w][tid];
        atomicAdd(&d_stats[s * 2 * DD + tid], a);
    }
}

extern "C" void kernel_launch(void* const* d_in, const int* in_sizes, int n_in,
                              void* d_out, int out_size) {
    const float* x     = (const float*)d_in[0];
    const int*   ei32  = (const int*)d_in[1];
    const float* attr  = (const float*)d_in[2];
    const int*   b32   = (const int*)d_in[3];
    const float* fc1_w  = (const float*)d_in[4],  *fc1_b  = (const float*)d_in[5];
    const float* fc2_w  = (const float*)d_in[6],  *fc2_b  = (const float*)d_in[7];
    const float* rfc1_w = (const float*)d_in[8],  *rfc1_b = (const float*)d_in[9];
    const float* rfc2_w = (const float*)d_in[10], *rfc2_b = (const float*)d_in[11];
    const float* fco_w  = (const float*)d_in[12], *fco_b  = (const float*)d_in[13];
    const float* bn1_g  = (const float*)d_in[14], *bn1_b  = (const float*)d_in[15];
    const float* bn2_g  = (const float*)d_in[16], *bn2_b  = (const float*)d_in[17];
    const float* rbn1_g = (const float*)d_in[18], *rbn1_b = (const float*)d_in[19];
    const float* rbn2_g = (const float*)d_in[20], *rbn2_b = (const float*)d_in[21];
    float* out = (float*)d_out;

    k_init<<<(GG * DD + 255) / 256, 256>>>(ei32, b32);
    k_scat<<<(EE + 511) / 512, 512>>>(x, ei32, attr, b32);
    k_gath<<<(GG * SL * 32 + 1023) / 1024, 1024>>>(x);

    k_stage<<<NHB, NHT>>>(0, fc1_w,  fc1_b,  nullptr, nullptr, nullptr);
    k_stage<<<NHB, NHT>>>(1, fc2_w,  fc2_b,  bn1_g,  bn1_b,  nullptr);
    k_stage<<<NHB, NHT>>>(2, rfc1_w, rfc1_b, bn2_g,  bn2_b,  nullptr);
    k_stage<<<NHB, NHT>>>(3, rfc2_w, rfc2_b, rbn1_g, rbn1_b, nullptr);
    k_stage<<<NHB, NHT>>>(4, fco_w,  fco_b,  rbn2_g, rbn2_b, out);
}